// round 13
// baseline (speedup 1.0000x reference)
#include <cuda_runtime.h>
#include <math.h>

#define NJ 23
#define NP 16
#define TPB 64          // threads per block
#define VPM 4           // vertices per thread
#define VPB (TPB*VPM)   // 256 vertices per block

__constant__ int c_par[NJ]  = {-1,0,1,1,3,4,5,4,7,4,9,1,11,12,13,12,15,12,17,0,19,0,21};
__constant__ int c_slot[NJ] = {0,-1,-1,1,2,3,-1,4,-1,5,-1,6,7,8,-1,9,-1,10,-1,-1,-1,-1,-1};
__constant__ float c_scale[11] = {
    0.7853981633974483f, 1.5707963267948966f, 1.5707963267948966f,
    0.7853981633974483f, 0.7853981633974483f, 0.7853981633974483f,
    1.5707963267948966f, 1.5707963267948966f, 0.7853981633974483f,
    0.7853981633974483f, 0.7853981633974483f};
__constant__ int c_lvl[NJ]  = {0,1,2,2,3,4,5,4,5,4,5,2,3,4,5,4,5,4,5,1,2,1,2};

struct Ptrs11 { const float* p[11]; };

// ---- f32x2 packed helpers (ptxas never emits these from C++) --------------
__device__ __forceinline__ void fma2(unsigned long long& d, unsigned long long a,
                                     unsigned long long b) {
    asm("fma.rn.f32x2 %0, %1, %2, %0;" : "+l"(d) : "l"(a), "l"(b));
}
__device__ __forceinline__ unsigned long long mul2(unsigned long long a,
                                                   unsigned long long b) {
    unsigned long long r;
    asm("mul.rn.f32x2 %0, %1, %2;" : "=l"(r) : "l"(a), "l"(b));
    return r;
}
__device__ __forceinline__ unsigned long long pack2(float lo, float hi) {
    unsigned long long r;
    asm("mov.b64 %0, {%1, %2};" : "=l"(r) : "f"(lo), "f"(hi));
    return r;
}
__device__ __forceinline__ void unpack2(unsigned long long v, float& lo, float& hi) {
    asm("mov.b64 {%0, %1}, %2;" : "=f"(lo), "=f"(hi) : "l"(v));
}

// ---------------------------------------------------------------------------
// Fused LBS. Phase 1 (replicated per block): pose kinematics. T lives in sA
// (aliased), G in sU (aliased); final packed A overwrites sA; weights slab
// overwrites sU. Phase 2: 4 vertices/thread, pose pairs in 2 passes of 4.
// Per thread: 1104 LDS.128 (A) : 8832 FFMA2  =  1:8.
// ---------------------------------------------------------------------------
__global__ void __launch_bounds__(TPB, 5)
lbs_fused_kernel(const float* __restrict__ verts,
                 const float* __restrict__ joints,
                 const float* __restrict__ weights,
                 const float* __restrict__ disp,
                 const float* __restrict__ rdis,
                 Ptrs11 prm,
                 float* __restrict__ out, int V)
{
    __shared__ __align__(16) float sA[NJ * 8 * 24];   // 17664 B: sT, then packed A
    __shared__ __align__(16) float sU[VPB * NJ];      // 23552 B: sG, then weights
    int t = threadIdx.x;

    // ================= Phase 1: pose (replicated in every block) ============
    // 368 (pose, joint) tasks over 64 threads: up to 6 per thread.
    #pragma unroll
    for (int k = 0; k < 6; k++) {
        int idx = t + k * TPB;
        if (idx < NP * NJ) {
            int p = idx / NJ, jj = idx - p * NJ;
            int s = c_slot[jj];
            float rx = 0.f, ry = 0.f, rz = 0.f;
            if (s >= 0) {
                const float* q = prm.p[s] + p * 3;
                float sc = c_scale[s];
                rx = sc * tanhf(q[0]); ry = sc * tanhf(q[1]); rz = sc * tanhf(q[2]);
            }
            float th = sqrtf(rx * rx + ry * ry + rz * rz + 1e-16f);
            float inv = 1.f / th;
            float ax = rx * inv, ay = ry * inv, az = rz * inv;
            float sn = sinf(th), cs = cosf(th), oc = 1.f - cs;
            float* T = &sA[idx * 12];
            T[0] = cs + oc * ax * ax;      T[1] = oc * ax * ay - sn * az; T[2]  = oc * ax * az + sn * ay;
            T[4] = oc * ax * ay + sn * az; T[5] = cs + oc * ay * ay;      T[6]  = oc * ay * az - sn * ax;
            T[8] = oc * ax * az - sn * ay; T[9] = oc * ay * az + sn * ax; T[10] = cs + oc * az * az;
            float relx = joints[jj * 3 + 0], rely = joints[jj * 3 + 1], relz = joints[jj * 3 + 2];
            if (jj > 0) {
                int pa = c_par[jj];
                relx -= joints[pa * 3 + 0];
                rely -= joints[pa * 3 + 1];
                relz -= joints[pa * 3 + 2];
            }
            T[3] = relx; T[7] = rely; T[11] = relz;
            if (jj == 0) {
                float* G = &sU[(p * NJ) * 12];
                #pragma unroll
                for (int i = 0; i < 12; i++) G[i] = T[i];
            }
        }
    }
    __syncthreads();

    // Kinematic chain, level by level (depth 5). G in sU, T in sA.
    #pragma unroll 1
    for (int l = 1; l <= 5; l++) {
        #pragma unroll
        for (int k = 0; k < 6; k++) {
            int idx = t + k * TPB;
            if (idx < NP * NJ) {
                int p = idx / NJ, jj = idx - p * NJ;
                if (c_lvl[jj] == l) {
                    const float* Gp = &sU[(p * NJ + c_par[jj]) * 12];
                    const float* T  = &sA[idx * 12];
                    float* Gc = &sU[idx * 12];
                    #pragma unroll
                    for (int i = 0; i < 3; i++) {
                        float a0 = Gp[i * 4 + 0], a1 = Gp[i * 4 + 1], a2 = Gp[i * 4 + 2];
                        Gc[i * 4 + 0] = a0 * T[0] + a1 * T[4] + a2 * T[8];
                        Gc[i * 4 + 1] = a0 * T[1] + a1 * T[5] + a2 * T[9];
                        Gc[i * 4 + 2] = a0 * T[2] + a1 * T[6] + a2 * T[10];
                        Gc[i * 4 + 3] = a0 * T[3] + a1 * T[7] + a2 * T[11] + Gp[i * 4 + 3];
                    }
                }
            }
        }
        __syncthreads();
    }

    // Pack A = [G_R | G_t - G_R@j + shift] -> sA (overwrites sT; T-reads done).
    #pragma unroll
    for (int k = 0; k < 6; k++) {
        int idx = t + k * TPB;
        if (idx < NP * NJ) {
            int p = idx / NJ, jj = idx - p * NJ;
            float sh0 = rdis[p * 3 + 0] + 3.f * tanhf(disp[p * 3 + 0]);
            float sh1 = rdis[p * 3 + 1] + 3.f * tanhf(disp[p * 3 + 1]);
            float sh2 = rdis[p * 3 + 2] + 3.f * tanhf(disp[p * 3 + 2]);
            float G[12];
            #pragma unroll
            for (int i = 0; i < 12; i++) G[i] = sU[idx * 12 + i];
            if (blockIdx.x == 0) {
                size_t jbase = (size_t)NP * V * 3 + ((size_t)p * NJ + jj) * 3;
                out[jbase + 0] = G[3]  + sh0;
                out[jbase + 1] = G[7]  + sh1;
                out[jbase + 2] = G[11] + sh2;
            }
            float jx = joints[jj * 3 + 0], jy = joints[jj * 3 + 1], jz = joints[jj * 3 + 2];
            int pp = p >> 1, par = p & 1;
            float* dst = sA + ((jj * 8 + pp) * 12) * 2 + par;
            float sh[3] = {sh0, sh1, sh2};
            #pragma unroll
            for (int i = 0; i < 3; i++) {
                float tr = G[i * 4 + 3] - (G[i * 4 + 0] * jx + G[i * 4 + 1] * jy + G[i * 4 + 2] * jz) + sh[i];
                dst[(i * 4 + 0) * 2] = G[i * 4 + 0];
                dst[(i * 4 + 1) * 2] = G[i * 4 + 1];
                dst[(i * 4 + 2) * 2] = G[i * 4 + 2];
                dst[(i * 4 + 3) * 2] = tr;
            }
        }
    }
    __syncthreads();   // packed A in sA done; sU (G) free

    // ================= Phase 2: skinning ====================================
    int base = blockIdx.x * VPB;
    {
        int rem = V - base;
        int nval = (rem >= VPB ? VPB : rem) * NJ;
        const float* slab = weights + (size_t)base * NJ;
        if (nval == VPB * NJ) {
            const float4* g4 = (const float4*)slab;
            float4* s4 = (float4*)sU;
            #pragma unroll 1
            for (int i = t; i < VPB * NJ / 4; i += TPB) s4[i] = g4[i];
        } else {
            #pragma unroll 1
            for (int i = t; i < nval; i += TPB) sU[i] = slab[i];
        }
    }
    __syncthreads();

    int vi[VPM];
    unsigned long long cx[VPM], cy[VPM], cz[VPM];
    #pragma unroll
    for (int m = 0; m < VPM; m++) {
        vi[m] = base + t + m * TPB;
        int vc = vi[m] < V ? vi[m] : V - 1;
        float x = verts[3 * vc + 0], y = verts[3 * vc + 1], z = verts[3 * vc + 2];
        cx[m] = pack2(x, x); cy[m] = pack2(y, y); cz[m] = pack2(z, z);
    }

    size_t slabsz = (size_t)V * 3;

    #pragma unroll 1
    for (int half = 0; half < 2; half++) {
        unsigned long long acc[VPM][4][3];
        #pragma unroll
        for (int m = 0; m < VPM; m++)
            #pragma unroll
            for (int pp = 0; pp < 4; pp++)
                #pragma unroll
                for (int i = 0; i < 3; i++) acc[m][pp][i] = 0ull;

        #pragma unroll 1
        for (int j = 0; j < NJ; j++) {
            unsigned long long wp[VPM], ax[VPM], ay[VPM], az[VPM];
            #pragma unroll
            for (int m = 0; m < VPM; m++) {
                float w = sU[(t + m * TPB) * NJ + j];
                wp[m] = pack2(w, w);
                ax[m] = mul2(wp[m], cx[m]);
                ay[m] = mul2(wp[m], cy[m]);
                az[m] = mul2(wp[m], cz[m]);
            }
            const ulonglong2* r = (const ulonglong2*)(sA + j * 8 * 24) + half * 24;
            #pragma unroll
            for (int pp = 0; pp < 4; pp++) {
                ulonglong2 q0 = r[pp * 6 + 0], q1 = r[pp * 6 + 1], q2 = r[pp * 6 + 2];
                ulonglong2 q3 = r[pp * 6 + 3], q4 = r[pp * 6 + 4], q5 = r[pp * 6 + 5];
                #pragma unroll
                for (int m = 0; m < VPM; m++) {
                    fma2(acc[m][pp][0], q0.x, ax[m]); fma2(acc[m][pp][0], q0.y, ay[m]);
                    fma2(acc[m][pp][0], q1.x, az[m]); fma2(acc[m][pp][0], q1.y, wp[m]);
                    fma2(acc[m][pp][1], q2.x, ax[m]); fma2(acc[m][pp][1], q2.y, ay[m]);
                    fma2(acc[m][pp][1], q3.x, az[m]); fma2(acc[m][pp][1], q3.y, wp[m]);
                    fma2(acc[m][pp][2], q4.x, ax[m]); fma2(acc[m][pp][2], q4.y, ay[m]);
                    fma2(acc[m][pp][2], q5.x, az[m]); fma2(acc[m][pp][2], q5.y, wp[m]);
                }
            }
        }

        #pragma unroll
        for (int m = 0; m < VPM; m++) {
            if (vi[m] < V) {
                size_t vb = (size_t)vi[m] * 3;
                #pragma unroll
                for (int pp = 0; pp < 4; pp++) {
                    int ppg = half * 4 + pp;
                    size_t c0 = (size_t)(2 * ppg) * slabsz + vb;
                    size_t c1 = c0 + slabsz;
                    #pragma unroll
                    for (int i = 0; i < 3; i++) {
                        float lo, hi;
                        unpack2(acc[m][pp][i], lo, hi);
                        out[c0 + i] = lo;
                        out[c1 + i] = hi;
                    }
                }
            }
        }
    }
}

// ---------------------------------------------------------------------------
// Launch: single fused kernel.
// ---------------------------------------------------------------------------
extern "C" void kernel_launch(void* const* d_in, const int* in_sizes, int n_in,
                              void* d_out, int out_size)
{
    const float* verts   = (const float*)d_in[0];
    const float* joints  = (const float*)d_in[1];
    const float* weights = (const float*)d_in[2];
    const float* disp    = (const float*)d_in[3];
    const float* rdis    = (const float*)d_in[4];
    Ptrs11 prm;
    for (int i = 0; i < 11; i++) prm.p[i] = (const float*)d_in[5 + i];
    int V = in_sizes[0] / 3;
    float* out = (float*)d_out;

    int nb = (V + VPB - 1) / VPB;
    lbs_fused_kernel<<<nb, TPB>>>(verts, joints, weights, disp, rdis, prm, out, V);
}